// round 1
// baseline (speedup 1.0000x reference)
#include <cuda_runtime.h>

#define N_EDGES 250000
#define N_NODES 10000
#define N_RBF   10
#define FEAT    144
#define P_TOTAL 4864
#define TILE_E  32
#define THREADS 256

// ---------------------------------------------------------------------------
// Per-path fully-unrolled worker.
//   IO = l_out, II = l_in, LF = filter l, CGOFF = offset into cg_flat.
// Lane layout within a warp:
//   m  = lane & 15   -> mul index (v for tmp phase, w for W/apply phase)
//   eh = lane >> 4   -> which pair of edges this half-warp owns
// Each warp owns 4 edges: lA = warp*4 + eh*2, lB = lA+1 (local tile indices).
// tmp[v][o] is computed in registers of lane v and fetched via shfl.
// Rt is the path's R block transposed to [r][v*16 + w] so that the lane=w
// read pattern (consecutive across lanes, duplicated across halves) is a
// conflict-free broadcast, and each LDS feeds 2 FMAs (two edges).
// ---------------------------------------------------------------------------
template<int IO, int II, int LF, int CGOFF>
__device__ __forceinline__ void do_path(
    const float* __restrict__ F_s,    // [TILE_E][FEAT]
    const float* __restrict__ Ys_s,   // [TILE_E][25]
    const float* __restrict__ cg_s,   // [1225]
    const float* __restrict__ Rt,     // [10][256] transposed
    const float* radA, const float* radB,
    int m, int lA, int lB,
    float* outA, float* outB)
{
    constexpr int DOUT = 2 * IO + 1;
    constexpr int DI   = 2 * II + 1;
    constexpr int DF   = 2 * LF + 1;
    constexpr int FOFF = (II == 0) ? 0 : ((II == 1) ? 16 : 64);
    constexpr int YOFF = LF * LF;
    const float NORM =
        (DF == 1) ? 1.0f :
        (DF == 3) ? 0.57735026918962576f :
        (DF == 5) ? 0.44721359549995794f :
        (DF == 7) ? 0.37796447300922723f :
                    0.33333333333333333f;

    // ---- tmp[v=m][o] for this half's two edges ----
    float FA[DI], FB[DI];
#pragma unroll
    for (int i = 0; i < DI; i++) {
        FA[i] = F_s[lA * FEAT + FOFF + m * DI + i];
        FB[i] = F_s[lB * FEAT + FOFF + m * DI + i];
    }
    float tA[DOUT], tB[DOUT];
#pragma unroll
    for (int o = 0; o < DOUT; o++) { tA[o] = 0.f; tB[o] = 0.f; }

#pragma unroll
    for (int f = 0; f < DF; f++) {
        float yA = Ys_s[lA * 25 + YOFF + f];
        float yB = Ys_s[lB * 25 + YOFF + f];
#pragma unroll
        for (int o = 0; o < DOUT; o++) {
            float gA = 0.f, gB = 0.f;
#pragma unroll
            for (int i = 0; i < DI; i++) {
                float c = cg_s[CGOFF + (o * DI + i) * DF + f];  // warp-broadcast
                gA += FA[i] * c;
                gB += FB[i] * c;
            }
            tA[o] += yA * gA;
            tB[o] += yB * gB;
        }
    }
#pragma unroll
    for (int o = 0; o < DOUT; o++) { tA[o] *= NORM; tB[o] *= NORM; }

    // ---- W[w=m][v] on the fly + apply via shfl ----
    float accA[DOUT], accB[DOUT];
#pragma unroll
    for (int o = 0; o < DOUT; o++) { accA[o] = 0.f; accB[o] = 0.f; }

#pragma unroll
    for (int v = 0; v < 16; v++) {
        float wA = 0.f, wB = 0.f;
#pragma unroll
        for (int r = 0; r < N_RBF; r++) {
            float rv = Rt[r * 256 + v * 16 + m];   // conflict-free, serves 2 edges
            wA += radA[r] * rv;
            wB += radB[r] * rv;
        }
#pragma unroll
        for (int o = 0; o < DOUT; o++) {
            float tvA = __shfl_sync(0xffffffffu, tA[o], v, 16);
            float tvB = __shfl_sync(0xffffffffu, tB[o], v, 16);
            accA[o] += wA * tvA;
            accB[o] += wB * tvB;
        }
    }
#pragma unroll
    for (int o = 0; o < DOUT; o++) { outA[o] += accA[o]; outB[o] += accB[o]; }
}

// ---------------------------------------------------------------------------
__global__ void __launch_bounds__(THREADS, 2)
conv_kernel(const float* __restrict__ features,
            const float* __restrict__ R,
            const float* __restrict__ Ys,
            const float* __restrict__ radii,
            const float* __restrict__ cg,
            const float* __restrict__ n_norm,
            const int*   __restrict__ map_a,
            const int*   __restrict__ map_b,
            float* __restrict__ out)
{
    __shared__ float Rt[N_RBF * 256];      // current path's R block, transposed
    __shared__ float cg_s[1225];
    __shared__ float F_s[TILE_E * FEAT];   // gathered source features
    __shared__ float Ys_s[TILE_E * 25];

    const int tid  = threadIdx.x;
    const int warp = tid >> 5;
    const int lane = tid & 31;
    const int m    = lane & 15;
    const int eh   = lane >> 4;
    const int e0   = blockIdx.x * TILE_E;

    // ---- stage block-wide data ----
    for (int i = tid; i < 1225; i += THREADS) cg_s[i] = cg[i];

    for (int idx = tid; idx < TILE_E * FEAT; idx += THREADS) {
        int le = idx / FEAT, c = idx - le * FEAT;
        int e  = e0 + le;
        int b  = (e < N_EDGES) ? map_b[e] : 0;
        F_s[idx] = features[b * FEAT + c];
    }
    for (int idx = tid; idx < TILE_E * 25; idx += THREADS) {
        int le = idx / 25, c = idx - le * 25;
        int e  = e0 + le;
        Ys_s[idx] = (e < N_EDGES) ? Ys[e * 25 + c] : 0.f;
    }

    // ---- per-lane edge bindings ----
    const int lA = warp * 4 + eh * 2;
    const int lB = lA + 1;
    const int eA = e0 + lA;
    const int eB = e0 + lB;
    const bool vA = (eA < N_EDGES);
    const bool vB = (eB < N_EDGES);

    float radA[N_RBF], radB[N_RBF];
#pragma unroll
    for (int r = 0; r < N_RBF; r++) {
        radA[r] = vA ? radii[eA * N_RBF + r] : 0.f;   // broadcast LDG per half
        radB[r] = vB ? radii[eB * N_RBF + r] : 0.f;
    }
    const int   aA  = vA ? map_a[eA] : 0;
    const int   aB  = vB ? map_a[eB] : 0;
    const float nnA = vA ? n_norm[aA] : 0.f;
    const float nnB = vB ? n_norm[aB] : 0.f;

    float outA[5], outB[5];
#pragma unroll
    for (int o = 0; o < 5; o++) { outA[o] = 0.f; outB[o] = 0.f; }

#define STAGE_R(P)                                                             \
    do {                                                                       \
        __syncthreads(); /* previous readers done (and initial staging) */     \
        for (int idx = tid; idx < N_RBF * 256; idx += THREADS) {               \
            int r = idx >> 8, c = idx & 255;                                   \
            /* Rt[r][ (c&15)*16 + (c>>4) ] = R[r][P*256 + c]  (w<->v swap) */  \
            Rt[(r << 8) | ((c & 15) << 4) | (c >> 4)] =                        \
                R[r * P_TOTAL + (P) * 256 + c];                                \
        }                                                                      \
        __syncthreads();                                                       \
    } while (0)

#define RUN(P, IO, II, LF, CGOFF)                                              \
    do {                                                                       \
        STAGE_R(P);                                                            \
        do_path<IO, II, LF, CGOFF>(F_s, Ys_s, cg_s, Rt, radA, radB,            \
                                   m, lA, lB, outA, outB);                     \
    } while (0)

    // ---------------- io = 0 (l_out = 0, DOUT = 1, out offset 0) ------------
    RUN(0, 0, 0, 0, 0);
    RUN(1, 0, 1, 1, 1);
    RUN(2, 0, 2, 2, 10);
    if (vA) atomicAdd(&out[aA * FEAT + m], nnA * outA[0]);
    if (vB) atomicAdd(&out[aB * FEAT + m], nnB * outB[0]);
#pragma unroll
    for (int o = 0; o < 5; o++) { outA[o] = 0.f; outB[o] = 0.f; }

    // ---------------- io = 1 (l_out = 1, DOUT = 3, out offset 16) -----------
    RUN(3, 1, 0, 1, 35);
    RUN(4, 1, 1, 0, 44);
    RUN(5, 1, 1, 1, 53);
    RUN(6, 1, 1, 2, 80);
    RUN(7, 1, 2, 1, 125);
    RUN(8, 1, 2, 2, 170);
    RUN(9, 1, 2, 3, 245);
#pragma unroll
    for (int o = 0; o < 3; o++) {
        if (vA) atomicAdd(&out[aA * FEAT + 16 + m * 3 + o], nnA * outA[o]);
        if (vB) atomicAdd(&out[aB * FEAT + 16 + m * 3 + o], nnB * outB[o]);
    }
#pragma unroll
    for (int o = 0; o < 5; o++) { outA[o] = 0.f; outB[o] = 0.f; }

    // ---------------- io = 2 (l_out = 2, DOUT = 5, out offset 64) -----------
    RUN(10, 2, 0, 2, 350);
    RUN(11, 2, 1, 1, 375);
    RUN(12, 2, 1, 2, 420);
    RUN(13, 2, 1, 3, 495);
    RUN(14, 2, 2, 0, 600);
    RUN(15, 2, 2, 1, 625);
    RUN(16, 2, 2, 2, 700);
    RUN(17, 2, 2, 3, 825);
    RUN(18, 2, 2, 4, 1000);
#pragma unroll
    for (int o = 0; o < 5; o++) {
        if (vA) atomicAdd(&out[aA * FEAT + 64 + m * 5 + o], nnA * outA[o]);
        if (vB) atomicAdd(&out[aB * FEAT + 64 + m * 5 + o], nnB * outB[o]);
    }

#undef RUN
#undef STAGE_R
}

// ---------------------------------------------------------------------------
extern "C" void kernel_launch(void* const* d_in, const int* in_sizes, int n_in,
                              void* d_out, int out_size)
{
    const float* features = (const float*)d_in[0];
    const float* R        = (const float*)d_in[1];
    const float* Ys       = (const float*)d_in[2];
    const float* radii    = (const float*)d_in[3];
    const float* cg       = (const float*)d_in[4];
    const float* n_norm   = (const float*)d_in[5];
    const int*   map_a    = (const int*)d_in[6];
    const int*   map_b    = (const int*)d_in[7];
    float*       out      = (float*)d_out;

    cudaMemsetAsync(out, 0, (size_t)out_size * sizeof(float));

    int grid = (N_EDGES + TILE_E - 1) / TILE_E;   // 7813
    conv_kernel<<<grid, THREADS>>>(features, R, Ys, radii, cg, n_norm,
                                   map_a, map_b, out);
}